// round 13
// baseline (speedup 1.0000x reference)
#include <cuda_runtime.h>
#include <cuda_fp16.h>
#include <cstdint>

// ===========================================================================
// ManualChebConv:  out[b] = sum_{k=0..4} T_k(L) (x[b] W_k) + bias
//  fp16 hi/lo split arithmetic:
//  1. copy_L: L -> fp16 hi/lo A slot 0
//  2. prep (fused): cheb1 (T2 = 2 L@L - I, 3-term fp16, first 32 blocks)
//     + build_u (U_k = x W_k via packed f32x2 FMA -> K-major fp16 B_hi;
//     U0+bias in out layout)
//  3. cheb2: [T3 | T4] = 2 T2 @ [T1 | T2] - [T1 | I]   (3-term fp16)
//  4. main HMMA GEMM, single-pass fp16 (A_hi@B_hi, K'=2048)
// ===========================================================================

#define NN    512
#define BATCH 1024
#define FIN   16
#define FOUT  8
#define CDIM  8192           // BATCH * FOUT
#define K2    2048           // 4 * NN (stacked Chebyshev K)
#define NCHUNK 32            // single fp16 term: 2048/64
#define STAGES 3
#define ACHUNK_BYTES 16384   // 128 rows * 128 B
#define BCHUNK_BYTES 16384
#define STAGE_BYTES  (ACHUNK_BYTES + BCHUNK_BYTES)
#define SMEM_TOTAL   (STAGES * STAGE_BYTES)

#define CH_STAGE_BYTES 24576 // A 64x128B (8KB) + B 128x128B (16KB)
#define CH_NCHUNK 24         // 3 terms * (512/64)

__device__ __half g_Ahi[NN * K2];            // [n][k], k = slot*512+m
__device__ __half g_Alo[NN * K2];
__device__ __half g_Bhi[(size_t)CDIM * K2];  // [c][k] K-major
__device__ float  g_U0b[(size_t)BATCH * NN * FOUT]; // U0+bias, [b][n][fo]

// ---------------------------------------------------------------------------
__device__ __forceinline__ uint32_t smem_u32(const void* p) {
    uint32_t a;
    asm("{ .reg .u64 t; cvta.to.shared.u64 t, %1; cvt.u32.u64 %0, t; }" : "=r"(a) : "l"(p));
    return a;
}
__device__ __forceinline__ uint32_t swz(uint32_t off) { return off ^ ((off >> 3) & 0x70); }

__device__ __forceinline__ void cp_async16(uint32_t dst, const void* src) {
    asm volatile("cp.async.cg.shared.global [%0], [%1], 16;\n" :: "r"(dst), "l"(src));
}
__device__ __forceinline__ void cp_commit() { asm volatile("cp.async.commit_group;\n" ::: "memory"); }
template <int N> __device__ __forceinline__ void cp_wait() {
    asm volatile("cp.async.wait_group %0;\n" :: "n"(N) : "memory");
}

__device__ __forceinline__ void ldm_x4(uint32_t& r0, uint32_t& r1, uint32_t& r2,
                                       uint32_t& r3, uint32_t addr) {
    asm volatile("ldmatrix.sync.aligned.m8n8.x4.shared.b16 {%0,%1,%2,%3}, [%4];"
                 : "=r"(r0), "=r"(r1), "=r"(r2), "=r"(r3) : "r"(addr));
}
__device__ __forceinline__ void mma_fp16(float* d, const uint32_t* a,
                                         const uint32_t* b) {
    asm volatile(
        "mma.sync.aligned.m16n8k16.row.col.f32.f16.f16.f32 "
        "{%0,%1,%2,%3}, {%4,%5,%6,%7}, {%8,%9}, {%0,%1,%2,%3};"
        : "+f"(d[0]), "+f"(d[1]), "+f"(d[2]), "+f"(d[3])
        : "r"(a[0]), "r"(a[1]), "r"(a[2]), "r"(a[3]), "r"(b[0]), "r"(b[1]));
}

// packed fp32x2 helpers (sm_100-family base ISA)
__device__ __forceinline__ uint64_t pack_f32x2(float v) {
    uint64_t r;
    asm("mov.b64 %0, {%1, %1};" : "=l"(r) : "f"(v));
    return r;
}
__device__ __forceinline__ void fma_f32x2(uint64_t& acc, uint64_t a, uint64_t b) {
    asm("fma.rn.f32x2 %0, %1, %2, %0;" : "+l"(acc) : "l"(a), "l"(b));
}
__device__ __forceinline__ void unpack_f32x2(float& lo, float& hi, uint64_t v) {
    asm("mov.b64 {%0, %1}, %2;" : "=f"(lo), "=f"(hi) : "l"(v));
}

// ---------------------------------------------------------------------------
// L -> fp16 hi/lo into A slot 0 (T1 = L).  grid 256 x 256 thr, 1 float4/thr.
// ---------------------------------------------------------------------------
__global__ void __launch_bounds__(256) copy_L_kernel(const float* __restrict__ L) {
    int idx4 = blockIdx.x * 256 + threadIdx.x;       // float4 index
    float4 v = reinterpret_cast<const float4*>(L)[idx4];
    int base = idx4 * 4;
    int n = base >> 9, m = base & 511;
    __half h[4], l[4];
    float vv[4] = {v.x, v.y, v.z, v.w};
    #pragma unroll
    for (int j = 0; j < 4; j++) {
        h[j] = __float2half_rn(vv[j]);
        l[j] = __float2half_rn(vv[j] - __half2float(h[j]));
    }
    size_t off = (size_t)n * K2 + m;
    *reinterpret_cast<uint64_t*>(&g_Ahi[off]) = *reinterpret_cast<uint64_t*>(h);
    *reinterpret_cast<uint64_t*>(&g_Alo[off]) = *reinterpret_cast<uint64_t*>(l);
}

// ---------------------------------------------------------------------------
// Cheb GEMM tile:  out = 2 * (A_slot @ B_slot) - D  over K=512, split-3 fp16.
// 64n x 128c tile, 256 threads (8 warps 2x4, warp 32x32), 2-stage pipeline.
// smemraw must provide 2 * CH_STAGE_BYTES = 48 KB.
// ---------------------------------------------------------------------------
__device__ __forceinline__ void cheb_tile(
    const float* __restrict__ L, char* smemraw,
    int aSlot, int bSlot, int outSlot, bool dIsL, int ccolBase, int nt)
{
    uint32_t sb = smem_u32(smemraw);
    int tid = threadIdx.x;
    int lane = tid & 31, w = tid >> 5;

    auto load_stage = [&](int s, int i) {
        int t  = i >> 3;                 // 0: hi@hi, 1: hi@lo, 2: lo@hi
        int kk = (i & 7) * 64;
        const __half* Asrc = (t == 2) ? g_Alo : g_Ahi;
        const __half* Bsrc = (t == 1) ? g_Alo : g_Ahi;
        uint32_t sA = sb + s * CH_STAGE_BYTES;
        uint32_t sB = sA + 8192;
        #pragma unroll
        for (int q = 0; q < 2; q++) {    // A: 64 rows x 128B
            int idx = q * 256 + tid;
            int row = idx >> 3, seg = idx & 7;
            const void* g = Asrc + (size_t)(nt * 64 + row) * K2 + aSlot * NN + kk + seg * 8;
            cp_async16(sA + swz(row * 128 + seg * 16), g);
        }
        #pragma unroll
        for (int q = 0; q < 4; q++) {    // B: 128 rows (cols, symmetric) x 128B
            int idx = q * 256 + tid;
            int row = idx >> 3, seg = idx & 7;
            const void* g = Bsrc + (size_t)(ccolBase + row) * K2 + bSlot * NN + kk + seg * 8;
            cp_async16(sB + swz(row * 128 + seg * 16), g);
        }
        cp_commit();
    };

    load_stage(0, 0);

    int wn = (w >> 2) * 32;              // 2 n-groups
    int wc = (w & 3) * 32;               // 4 c-groups
    int rowA  = wn + (lane & 15);
    int halfA = lane >> 4;
    int rowB  = wc + ((lane >> 4) & 1) * 8 + (lane & 7);
    int kselB = (lane >> 3) & 1;

    float acc[2][4][4] = {};

    for (int i = 0; i < CH_NCHUNK; i++) {
        int s = i & 1;
        cp_wait<0>();
        __syncthreads();
        if (i + 1 < CH_NCHUNK) load_stage((i + 1) & 1, i + 1);

        uint32_t sA = sb + s * CH_STAGE_BYTES;
        uint32_t sB = sA + 8192;

        #pragma unroll
        for (int kk = 0; kk < 4; kk++) {
            uint32_t a[2][4];
            #pragma unroll
            for (int m2 = 0; m2 < 2; m2++) {
                uint32_t addr = sA + swz((rowA + m2 * 16) * 128 + (kk * 2 + halfA) * 16);
                ldm_x4(a[m2][0], a[m2][1], a[m2][2], a[m2][3], addr);
            }
            #pragma unroll
            for (int cg = 0; cg < 2; cg++) {
                uint32_t b[4];
                uint32_t addr = sB + swz((rowB + cg * 16) * 128 + (kk * 2 + kselB) * 16);
                ldm_x4(b[0], b[1], b[2], b[3], addr);
                #pragma unroll
                for (int m2 = 0; m2 < 2; m2++) {
                    mma_fp16(acc[m2][2 * cg + 0], a[m2], b + 0);
                    mma_fp16(acc[m2][2 * cg + 1], a[m2], b + 2);
                }
            }
        }
        __syncthreads();   // protect stage s before it is reloaded at i+2
    }

    // Epilogue: v = 2*acc - D; emit fp16 hi/lo into stacked A array.
    int tr = lane >> 2, tc2 = (lane & 3) * 2;
    #pragma unroll
    for (int m2 = 0; m2 < 2; m2++) {
        #pragma unroll
        for (int cf = 0; cf < 4; cf++) {
            #pragma unroll
            for (int rr = 0; rr < 2; rr++) {
                int n  = nt * 64 + wn + m2 * 16 + tr + rr * 8;
                int cc = ccolBase + wc + cf * 8 + tc2;
                float d0, d1;
                if (dIsL) {
                    d0 = L[(size_t)n * NN + cc];
                    d1 = L[(size_t)n * NN + cc + 1];
                } else {
                    d0 = (n == cc)     ? 1.0f : 0.0f;
                    d1 = (n == cc + 1) ? 1.0f : 0.0f;
                }
                float v0 = 2.0f * acc[m2][cf][rr * 2 + 0] - d0;
                float v1 = 2.0f * acc[m2][cf][rr * 2 + 1] - d1;
                __half h0 = __float2half_rn(v0);
                __half h1 = __float2half_rn(v1);
                __half2 hv(h0, h1);
                __half2 lv(__float2half_rn(v0 - __half2float(h0)),
                           __float2half_rn(v1 - __half2float(h1)));
                size_t off = (size_t)n * K2 + outSlot * NN + cc;
                *reinterpret_cast<__half2*>(&g_Ahi[off]) = hv;
                *reinterpret_cast<__half2*>(&g_Alo[off]) = lv;
            }
        }
    }
}

// ---------------------------------------------------------------------------
// Fused prep kernel, grid (256, 9):
//  y == 0, bx < 32 : cheb1 tile (T2 = 2 L@L - I); bx >= 32: idle.
//  y >= 1 : build_u with bym = y-1 (packed f32x2 FMA):
//    k=0  -> g_U0b = U0 + bias (out layout)
//    k>=1 -> g_Bhi K-major via half-staged smem transpose
// ---------------------------------------------------------------------------
__global__ void __launch_bounds__(256) prep_kernel(
    const float* __restrict__ x, const float* __restrict__ W,
    const float* __restrict__ bias, const float* __restrict__ L)
{
    __shared__ alignas(16) char buf[49152];
    int tid = threadIdx.x;
    int bx = blockIdx.x;

    if (blockIdx.y == 0) {
        if (bx >= 32) return;
        int ct = bx & 3, nt = bx >> 2;
        cheb_tile(L, buf, 0, 0, 1, false, ct * 128, nt);   // T2 = 2 L@L - I
        return;
    }

    // ---- build_u ----
    float* Ws = reinterpret_cast<float*>(buf);                       // 640 floats
    __half (*tsh)[32][72] = reinterpret_cast<__half (*)[32][72]>(buf + 2560);

    for (int i = tid; i < 5 * FIN * FOUT; i += 256) Ws[i] = W[i];
    __syncthreads();

    int bym = blockIdx.y - 1;                  // m-tile of 64
    int b_l = tid >> 6, m_l = tid & 63;
    int b = bx * 4 + b_l, m = bym * 64 + m_l;

    // load x row and pack into broadcast f32x2 pairs
    uint64_t xx2[16];
    {
        const float4* xp = reinterpret_cast<const float4*>(x + ((size_t)b * NN + m) * FIN);
        #pragma unroll
        for (int q = 0; q < 4; q++) {
            float4 v = xp[q];
            xx2[q * 4 + 0] = pack_f32x2(v.x);
            xx2[q * 4 + 1] = pack_f32x2(v.y);
            xx2[q * 4 + 2] = pack_f32x2(v.z);
            xx2[q * 4 + 3] = pack_f32x2(v.w);
        }
    }

    // k = 0 : direct write, bias folded
    {
        uint64_t acc2[4] = {0ull, 0ull, 0ull, 0ull};
        #pragma unroll
        for (int fi = 0; fi < 16; fi++) {
            const uint64_t* wp = reinterpret_cast<const uint64_t*>(&Ws[fi * 8]);
            #pragma unroll
            for (int j = 0; j < 4; j++) fma_f32x2(acc2[j], xx2[fi], wp[j]);
        }
        float a[8];
        #pragma unroll
        for (int j = 0; j < 4; j++) unpack_f32x2(a[2 * j], a[2 * j + 1], acc2[j]);
        float* dst = g_U0b + ((size_t)b * NN + m) * FOUT;
        float4 o0 = {a[0] + bias[0], a[1] + bias[1], a[2] + bias[2], a[3] + bias[3]};
        float4 o1 = {a[4] + bias[4], a[5] + bias[5], a[6] + bias[6], a[7] + bias[7]};
        reinterpret_cast<float4*>(dst)[0] = o0;
        reinterpret_cast<float4*>(dst)[1] = o1;
    }

    // k = 1..4 : packed FMA, convert to fp16, stage for transpose
    #pragma unroll
    for (int kc = 0; kc < 4; kc++) {
        uint64_t acc2[4] = {0ull, 0ull, 0ull, 0ull};
        #pragma unroll
        for (int fi = 0; fi < 16; fi++) {
            const uint64_t* wp = reinterpret_cast<const uint64_t*>(&Ws[((kc + 1) * 16 + fi) * 8]);
            #pragma unroll
            for (int j = 0; j < 4; j++) fma_f32x2(acc2[j], xx2[fi], wp[j]);
        }
        #pragma unroll
        for (int j = 0; j < 4; j++) {
            float lo, hi;
            unpack_f32x2(lo, hi, acc2[j]);
            tsh[kc][b_l * 8 + 2 * j + 0][m_l] = __float2half_rn(lo);
            tsh[kc][b_l * 8 + 2 * j + 1][m_l] = __float2half_rn(hi);
        }
    }
    __syncthreads();

    // transposed read: one 16B LDS + one 16B STG per kc
    int row = tid >> 3, seg = tid & 7;         // row = local c (0..31)
    int c_out = bx * 32 + row;
    #pragma unroll
    for (int kc = 0; kc < 4; kc++) {
        uint4 v = *reinterpret_cast<const uint4*>(&tsh[kc][row][seg * 8]);
        size_t off = (size_t)c_out * K2 + (size_t)kc * NN + bym * 64 + seg * 8;
        *reinterpret_cast<uint4*>(&g_Bhi[off]) = v;
    }
}

// ---------------------------------------------------------------------------
// cheb2: [T3 | T4] = 2 T2 @ [T1 | T2] - [T1 | I].  grid (8, 8), 256 thr.
// ---------------------------------------------------------------------------
__global__ void __launch_bounds__(256) cheb2_kernel(const float* __restrict__ L)
{
    __shared__ alignas(16) char buf[49152];
    int ct = blockIdx.x, nt = blockIdx.y;
    int half = ct >> 2;
    cheb_tile(L, buf, /*aSlot=*/1, /*bSlot=*/half ? 1 : 0,
              /*outSlot=*/half ? 3 : 2, /*dIsL=*/half == 0,
              (ct & 3) * 128, nt);
}

// ---------------------------------------------------------------------------
// Main HMMA GEMM: C[n=512][c=8192] over K'=2048 (single fp16 pass).
// CTA 128x128, 8 warps (4x2), warp 32x64. Grid (64,4), occ 2.
// ---------------------------------------------------------------------------
__global__ void __launch_bounds__(256, 2) hmma_gemm_kernel(float* __restrict__ out)
{
    extern __shared__ char smem[];
    uint32_t sb = smem_u32(smem);
    int tid = threadIdx.x;
    int lane = tid & 31, w = tid >> 5;
    int bx = blockIdx.x;    // c-tile (128 wide)
    int by = blockIdx.y;    // n-tile (128 wide)

    auto load_stage = [&](int s, int i) {
        int kk = i * 64;
        uint32_t sA = sb + s * STAGE_BYTES;
        uint32_t sB = sA + ACHUNK_BYTES;
        #pragma unroll
        for (int q = 0; q < 4; q++) {
            int idx = q * 256 + tid;
            int row = idx >> 3, seg = idx & 7;
            const void* g = g_Ahi + (size_t)(by * 128 + row) * K2 + kk + seg * 8;
            cp_async16(sA + swz(row * 128 + seg * 16), g);
        }
        #pragma unroll
        for (int q = 0; q < 4; q++) {
            int idx = q * 256 + tid;
            int row = idx >> 3, seg = idx & 7;
            const void* g = g_Bhi + (size_t)(bx * 128 + row) * K2 + kk + seg * 8;
            cp_async16(sB + swz(row * 128 + seg * 16), g);
        }
        cp_commit();
    };

    load_stage(0, 0);
    load_stage(1, 1);

    int warp_n0 = (w >> 1) * 32;
    int warp_c0 = (w & 1) * 64;
    int rowA  = warp_n0 + (lane & 15);
    int halfA = lane >> 4;
    int rowB  = warp_c0 + ((lane >> 4) & 1) * 8 + (lane & 7);
    int kselB = (lane >> 3) & 1;

    float acc[2][8][4] = {};

    for (int i = 0; i < NCHUNK; i++) {
        int s = i % STAGES;
        if (i < NCHUNK - 1) cp_wait<1>();
        else                cp_wait<0>();
        __syncthreads();
        if (i + 2 < NCHUNK) load_stage((i + 2) % STAGES, i + 2);

        uint32_t sA = sb + s * STAGE_BYTES;
        uint32_t sB = sA + ACHUNK_BYTES;

        #pragma unroll
        for (int kk = 0; kk < 4; kk++) {
            uint32_t a[2][4];
            #pragma unroll
            for (int m2 = 0; m2 < 2; m2++) {
                uint32_t addr = sA + swz((rowA + m2 * 16) * 128 + (kk * 2 + halfA) * 16);
                ldm_x4(a[m2][0], a[m2][1], a[m2][2], a[m2][3], addr);
            }
            #pragma unroll
            for (int cg = 0; cg < 4; cg++) {
                uint32_t b[4];
                uint32_t addr = sB + swz((rowB + cg * 16) * 128 + (kk * 2 + kselB) * 16);
                ldm_x4(b[0], b[1], b[2], b[3], addr);
                #pragma unroll
                for (int m2 = 0; m2 < 2; m2++) {
                    mma_fp16(acc[m2][2 * cg + 0], a[m2], b + 0);
                    mma_fp16(acc[m2][2 * cg + 1], a[m2], b + 2);
                }
            }
        }
    }

    // Epilogue: + (U0 + bias), write out[b][n][fo]
    int tr = lane >> 2, tc2 = (lane & 3) * 2;
    #pragma unroll
    for (int m2 = 0; m2 < 2; m2++) {
        #pragma unroll
        for (int ct = 0; ct < 8; ct++) {
            int c = bx * 128 + warp_c0 + ct * 8 + tc2;
            int b = c >> 3;
            int n0 = by * 128 + warp_n0 + m2 * 16 + tr;
            size_t o0 = ((size_t)b * NN + n0) * FOUT + tc2;
            size_t o1 = o0 + 8 * FOUT;
            float2 u0 = *reinterpret_cast<const float2*>(&g_U0b[o0]);
            float2 u1 = *reinterpret_cast<const float2*>(&g_U0b[o1]);
            float2 r0 = {acc[m2][ct][0] + u0.x, acc[m2][ct][1] + u0.y};
            float2 r1 = {acc[m2][ct][2] + u1.x, acc[m2][ct][3] + u1.y};
            *reinterpret_cast<float2*>(&out[o0]) = r0;
            *reinterpret_cast<float2*>(&out[o1]) = r1;
        }
    }
}

// ---------------------------------------------------------------------------
extern "C" void kernel_launch(void* const* d_in, const int* in_sizes, int n_in,
                              void* d_out, int out_size)
{
    const float* x = (const float*)d_in[0];  // [1024, 512, 16]
    const float* L = (const float*)d_in[1];  // [512, 512]
    const float* W = (const float*)d_in[2];  // [5, 16, 8]
    const float* b = (const float*)d_in[3];  // [8]
    float* out = (float*)d_out;              // [1024, 512, 8]

    cudaFuncSetAttribute(hmma_gemm_kernel,
                         cudaFuncAttributeMaxDynamicSharedMemorySize, SMEM_TOTAL);

    copy_L_kernel<<<256, 256>>>(L);                    // T1 hi/lo
    prep_kernel<<<dim3(256, 9), 256>>>(x, W, b, L);    // build_u + cheb1
    cheb2_kernel<<<dim3(8, 8), 256>>>(L);              // T3, T4
    hmma_gemm_kernel<<<dim3(64, 4), 256, SMEM_TOTAL>>>(out);
}

// round 14
// speedup vs baseline: 1.1352x; 1.1352x over previous
#include <cuda_runtime.h>
#include <cuda_fp16.h>
#include <cstdint>

// ===========================================================================
// ManualChebConv:  out[b] = sum_{k=0..4} T_k(L) (x[b] W_k) + bias
//  fp16 hi/lo split arithmetic:
//  1. copy_L: L -> fp16 hi/lo A slot 0
//  2. prep (fused): cheb1 (T2 = 2 L@L - I, 3-term fp16, first 32 blocks)
//     + TENSORIZED build_u: U = x@W as m16n8k16 HMMA ([256x16]@[16x40]
//     per block) -> K-major fp16 B_hi + U0+bias in out layout
//  3. cheb2: [T3 | T4] = 2 T2 @ [T1 | T2] - [T1 | I]   (3-term fp16)
//  4. main HMMA GEMM, single-pass fp16 (A_hi@B_hi, K'=2048)
// ===========================================================================

#define NN    512
#define BATCH 1024
#define FIN   16
#define FOUT  8
#define CDIM  8192           // BATCH * FOUT
#define K2    2048           // 4 * NN (stacked Chebyshev K)
#define NCHUNK 32            // single fp16 term: 2048/64
#define STAGES 3
#define ACHUNK_BYTES 16384   // 128 rows * 128 B
#define BCHUNK_BYTES 16384
#define STAGE_BYTES  (ACHUNK_BYTES + BCHUNK_BYTES)
#define SMEM_TOTAL   (STAGES * STAGE_BYTES)

#define CH_STAGE_BYTES 24576 // A 64x128B (8KB) + B 128x128B (16KB)
#define CH_NCHUNK 24         // 3 terms * (512/64)

__device__ __half g_Ahi[NN * K2];            // [n][k], k = slot*512+m
__device__ __half g_Alo[NN * K2];
__device__ __half g_Bhi[(size_t)CDIM * K2];  // [c][k] K-major
__device__ float  g_U0b[(size_t)BATCH * NN * FOUT]; // U0+bias, [b][n][fo]

// ---------------------------------------------------------------------------
__device__ __forceinline__ uint32_t smem_u32(const void* p) {
    uint32_t a;
    asm("{ .reg .u64 t; cvta.to.shared.u64 t, %1; cvt.u32.u64 %0, t; }" : "=r"(a) : "l"(p));
    return a;
}
__device__ __forceinline__ uint32_t swz(uint32_t off) { return off ^ ((off >> 3) & 0x70); }

__device__ __forceinline__ void cp_async16(uint32_t dst, const void* src) {
    asm volatile("cp.async.cg.shared.global [%0], [%1], 16;\n" :: "r"(dst), "l"(src));
}
__device__ __forceinline__ void cp_commit() { asm volatile("cp.async.commit_group;\n" ::: "memory"); }
template <int N> __device__ __forceinline__ void cp_wait() {
    asm volatile("cp.async.wait_group %0;\n" :: "n"(N) : "memory");
}

__device__ __forceinline__ void ldm_x4(uint32_t& r0, uint32_t& r1, uint32_t& r2,
                                       uint32_t& r3, uint32_t addr) {
    asm volatile("ldmatrix.sync.aligned.m8n8.x4.shared.b16 {%0,%1,%2,%3}, [%4];"
                 : "=r"(r0), "=r"(r1), "=r"(r2), "=r"(r3) : "r"(addr));
}
__device__ __forceinline__ void ldm_x2(uint32_t& r0, uint32_t& r1, uint32_t addr) {
    asm volatile("ldmatrix.sync.aligned.m8n8.x2.shared.b16 {%0,%1}, [%2];"
                 : "=r"(r0), "=r"(r1) : "r"(addr));
}
__device__ __forceinline__ void mma_fp16(float* d, const uint32_t* a,
                                         const uint32_t* b) {
    asm volatile(
        "mma.sync.aligned.m16n8k16.row.col.f32.f16.f16.f32 "
        "{%0,%1,%2,%3}, {%4,%5,%6,%7}, {%8,%9}, {%0,%1,%2,%3};"
        : "+f"(d[0]), "+f"(d[1]), "+f"(d[2]), "+f"(d[3])
        : "r"(a[0]), "r"(a[1]), "r"(a[2]), "r"(a[3]), "r"(b[0]), "r"(b[1]));
}

// ---------------------------------------------------------------------------
// L -> fp16 hi/lo into A slot 0 (T1 = L).  grid 256 x 256 thr, 1 float4/thr.
// ---------------------------------------------------------------------------
__global__ void __launch_bounds__(256) copy_L_kernel(const float* __restrict__ L) {
    int idx4 = blockIdx.x * 256 + threadIdx.x;       // float4 index
    float4 v = reinterpret_cast<const float4*>(L)[idx4];
    int base = idx4 * 4;
    int n = base >> 9, m = base & 511;
    __half h[4], l[4];
    float vv[4] = {v.x, v.y, v.z, v.w};
    #pragma unroll
    for (int j = 0; j < 4; j++) {
        h[j] = __float2half_rn(vv[j]);
        l[j] = __float2half_rn(vv[j] - __half2float(h[j]));
    }
    size_t off = (size_t)n * K2 + m;
    *reinterpret_cast<uint64_t*>(&g_Ahi[off]) = *reinterpret_cast<uint64_t*>(h);
    *reinterpret_cast<uint64_t*>(&g_Alo[off]) = *reinterpret_cast<uint64_t*>(l);
}

// ---------------------------------------------------------------------------
// Cheb GEMM tile:  out = 2 * (A_slot @ B_slot) - D  over K=512, split-3 fp16.
// 64n x 128c tile, 256 threads (8 warps 2x4, warp 32x32), 2-stage pipeline.
// smemraw must provide 2 * CH_STAGE_BYTES = 48 KB.
// ---------------------------------------------------------------------------
__device__ __forceinline__ void cheb_tile(
    const float* __restrict__ L, char* smemraw,
    int aSlot, int bSlot, int outSlot, bool dIsL, int ccolBase, int nt)
{
    uint32_t sb = smem_u32(smemraw);
    int tid = threadIdx.x;
    int lane = tid & 31, w = tid >> 5;

    auto load_stage = [&](int s, int i) {
        int t  = i >> 3;                 // 0: hi@hi, 1: hi@lo, 2: lo@hi
        int kk = (i & 7) * 64;
        const __half* Asrc = (t == 2) ? g_Alo : g_Ahi;
        const __half* Bsrc = (t == 1) ? g_Alo : g_Ahi;
        uint32_t sA = sb + s * CH_STAGE_BYTES;
        uint32_t sB = sA + 8192;
        #pragma unroll
        for (int q = 0; q < 2; q++) {    // A: 64 rows x 128B
            int idx = q * 256 + tid;
            int row = idx >> 3, seg = idx & 7;
            const void* g = Asrc + (size_t)(nt * 64 + row) * K2 + aSlot * NN + kk + seg * 8;
            cp_async16(sA + swz(row * 128 + seg * 16), g);
        }
        #pragma unroll
        for (int q = 0; q < 4; q++) {    // B: 128 rows (cols, symmetric) x 128B
            int idx = q * 256 + tid;
            int row = idx >> 3, seg = idx & 7;
            const void* g = Bsrc + (size_t)(ccolBase + row) * K2 + bSlot * NN + kk + seg * 8;
            cp_async16(sB + swz(row * 128 + seg * 16), g);
        }
        cp_commit();
    };

    load_stage(0, 0);

    int wn = (w >> 2) * 32;              // 2 n-groups
    int wc = (w & 3) * 32;               // 4 c-groups
    int rowA  = wn + (lane & 15);
    int halfA = lane >> 4;
    int rowB  = wc + ((lane >> 4) & 1) * 8 + (lane & 7);
    int kselB = (lane >> 3) & 1;

    float acc[2][4][4] = {};

    for (int i = 0; i < CH_NCHUNK; i++) {
        int s = i & 1;
        cp_wait<0>();
        __syncthreads();
        if (i + 1 < CH_NCHUNK) load_stage((i + 1) & 1, i + 1);

        uint32_t sA = sb + s * CH_STAGE_BYTES;
        uint32_t sB = sA + 8192;

        #pragma unroll
        for (int kk = 0; kk < 4; kk++) {
            uint32_t a[2][4];
            #pragma unroll
            for (int m2 = 0; m2 < 2; m2++) {
                uint32_t addr = sA + swz((rowA + m2 * 16) * 128 + (kk * 2 + halfA) * 16);
                ldm_x4(a[m2][0], a[m2][1], a[m2][2], a[m2][3], addr);
            }
            #pragma unroll
            for (int cg = 0; cg < 2; cg++) {
                uint32_t b[4];
                uint32_t addr = sB + swz((rowB + cg * 16) * 128 + (kk * 2 + kselB) * 16);
                ldm_x4(b[0], b[1], b[2], b[3], addr);
                #pragma unroll
                for (int m2 = 0; m2 < 2; m2++) {
                    mma_fp16(acc[m2][2 * cg + 0], a[m2], b + 0);
                    mma_fp16(acc[m2][2 * cg + 1], a[m2], b + 2);
                }
            }
        }
        __syncthreads();   // protect stage s before it is reloaded at i+2
    }

    // Epilogue: v = 2*acc - D; emit fp16 hi/lo into stacked A array.
    int tr = lane >> 2, tc2 = (lane & 3) * 2;
    #pragma unroll
    for (int m2 = 0; m2 < 2; m2++) {
        #pragma unroll
        for (int cf = 0; cf < 4; cf++) {
            #pragma unroll
            for (int rr = 0; rr < 2; rr++) {
                int n  = nt * 64 + wn + m2 * 16 + tr + rr * 8;
                int cc = ccolBase + wc + cf * 8 + tc2;
                float d0, d1;
                if (dIsL) {
                    d0 = L[(size_t)n * NN + cc];
                    d1 = L[(size_t)n * NN + cc + 1];
                } else {
                    d0 = (n == cc)     ? 1.0f : 0.0f;
                    d1 = (n == cc + 1) ? 1.0f : 0.0f;
                }
                float v0 = 2.0f * acc[m2][cf][rr * 2 + 0] - d0;
                float v1 = 2.0f * acc[m2][cf][rr * 2 + 1] - d1;
                __half h0 = __float2half_rn(v0);
                __half h1 = __float2half_rn(v1);
                __half2 hv(h0, h1);
                __half2 lv(__float2half_rn(v0 - __half2float(h0)),
                           __float2half_rn(v1 - __half2float(h1)));
                size_t off = (size_t)n * K2 + outSlot * NN + cc;
                *reinterpret_cast<__half2*>(&g_Ahi[off]) = hv;
                *reinterpret_cast<__half2*>(&g_Alo[off]) = lv;
            }
        }
    }
}

// ---------------------------------------------------------------------------
// Fused prep kernel, grid (256, 9):
//  y == 0, bx < 32 : cheb1 tile (T2 = 2 L@L - I); bx >= 32: idle.
//  y >= 1 : tensorized build_u; block = 1 batch x 256 nodes:
//    U[256 x 40] = x_slice[256 x 16] @ Wt[40 x 16]^T  (fp16 HMMA, K=16)
//    cheb k=0 -> g_U0b (+bias); k=1..4 -> g_Bhi K-major via smem staging
// ---------------------------------------------------------------------------
__global__ void __launch_bounds__(256) prep_kernel(
    const float* __restrict__ x, const float* __restrict__ W,
    const float* __restrict__ bias, const float* __restrict__ L)
{
    __shared__ alignas(16) char buf[49152];
    int tid = threadIdx.x;
    int bx = blockIdx.x;

    if (blockIdx.y == 0) {
        if (bx >= 32) return;
        int ct = bx & 3, nt = bx >> 2;
        cheb_tile(L, buf, 0, 0, 1, false, ct * 128, nt);   // T2 = 2 L@L - I
        return;
    }

    // ---- tensorized build_u ----
    // smem layout: sA rows 256 x 48B @0 (12288), sW 40 x 48B @12288 (1920),
    //              tsh [4][8][256] halves @14208 (16384)
    int blockid = (blockIdx.y - 1) * 256 + bx;   // 0..2047
    int b  = blockid >> 1;
    int m0 = (blockid & 1) * 256;
    int lane = tid & 31, w = tid >> 5;
    uint32_t sbase = smem_u32(buf);

    // x slice -> fp16 sA (48B row stride, conflict-free ldmatrix phases)
    {
        const float4* xp = reinterpret_cast<const float4*>(
            x + ((size_t)b * NN + m0 + tid) * FIN);
        __half2 h2[8];
        #pragma unroll
        for (int q = 0; q < 4; q++) {
            float4 v = xp[q];
            h2[q * 2 + 0] = __floats2half2_rn(v.x, v.y);
            h2[q * 2 + 1] = __floats2half2_rn(v.z, v.w);
        }
        char* rowp = buf + tid * 48;
        *reinterpret_cast<uint4*>(rowp)      = reinterpret_cast<uint4*>(h2)[0];
        *reinterpret_cast<uint4*>(rowp + 16) = reinterpret_cast<uint4*>(h2)[1];
    }
    // W -> Wt[n=kcheb*8+fo][fi] fp16 (48B row stride)
    for (int idx = tid; idx < 640; idx += 256) {
        int n = idx >> 4, fi = idx & 15;
        int k = n >> 3, fo = n & 7;
        *reinterpret_cast<__half*>(buf + 12288 + n * 48 + fi * 2) =
            __float2half_rn(W[(k * 16 + fi) * 8 + fo]);
    }
    __syncthreads();

    // fragments
    uint32_t a[2][4];
    #pragma unroll
    for (int m2 = 0; m2 < 2; m2++) {
        uint32_t addr = sbase + (w * 32 + m2 * 16 + (lane & 15)) * 48 + (lane >> 4) * 16;
        ldm_x4(a[m2][0], a[m2][1], a[m2][2], a[m2][3], addr);
    }
    uint32_t bf[5][2];
    {
        uint32_t wb = sbase + 12288;
        int rb = ((lane >> 4) & 1) * 8 + (lane & 7);
        int ks = (lane >> 3) & 1;
        uint32_t t4[4];
        ldm_x4(t4[0], t4[1], t4[2], t4[3], wb + rb * 48 + ks * 16);
        bf[0][0] = t4[0]; bf[0][1] = t4[1]; bf[1][0] = t4[2]; bf[1][1] = t4[3];
        ldm_x4(t4[0], t4[1], t4[2], t4[3], wb + (16 + rb) * 48 + ks * 16);
        bf[2][0] = t4[0]; bf[2][1] = t4[1]; bf[3][0] = t4[2]; bf[3][1] = t4[3];
        ldm_x2(bf[4][0], bf[4][1], wb + (32 + (lane & 7)) * 48 + ((lane >> 3) & 1) * 16);
    }

    float acc[2][5][4] = {};
    #pragma unroll
    for (int m2 = 0; m2 < 2; m2++)
        #pragma unroll
        for (int kc = 0; kc < 5; kc++)
            mma_fp16(acc[m2][kc], a[m2], bf[kc]);

    // epilogue
    int tr = lane >> 2, tc2 = (lane & 3) * 2;
    float bs0 = bias[tc2], bs1 = bias[tc2 + 1];
    __half* tsh = reinterpret_cast<__half*>(buf + 14208);

    #pragma unroll
    for (int m2 = 0; m2 < 2; m2++) {
        int rl = w * 32 + m2 * 16 + tr;
        size_t r = (size_t)blockid * 256 + rl;
        float2 v0 = {acc[m2][0][0] + bs0, acc[m2][0][1] + bs1};
        float2 v1 = {acc[m2][0][2] + bs0, acc[m2][0][3] + bs1};
        *reinterpret_cast<float2*>(&g_U0b[r * 8 + tc2])       = v0;
        *reinterpret_cast<float2*>(&g_U0b[(r + 8) * 8 + tc2]) = v1;
        #pragma unroll
        for (int kc = 0; kc < 4; kc++) {
            tsh[(kc * 8 + tc2)     * 256 + rl]     = __float2half_rn(acc[m2][kc + 1][0]);
            tsh[(kc * 8 + tc2 + 1) * 256 + rl]     = __float2half_rn(acc[m2][kc + 1][1]);
            tsh[(kc * 8 + tc2)     * 256 + rl + 8] = __float2half_rn(acc[m2][kc + 1][2]);
            tsh[(kc * 8 + tc2 + 1) * 256 + rl + 8] = __float2half_rn(acc[m2][kc + 1][3]);
        }
    }
    __syncthreads();

    // readout: 1024 16B tasks; each warp streams one (kc,fo) row contiguously
    #pragma unroll
    for (int it = 0; it < 4; it++) {
        int id = it * 256 + tid;
        int kcfo = id >> 5;                  // kc*8+fo
        int seg  = id & 31;
        int kc = kcfo >> 3, fo = kcfo & 7;
        uint4 v = *reinterpret_cast<const uint4*>(&tsh[kcfo * 256 + seg * 8]);
        size_t off = (size_t)(b * 8 + fo) * K2 + (size_t)kc * NN + m0 + seg * 8;
        *reinterpret_cast<uint4*>(&g_Bhi[off]) = v;
    }
}

// ---------------------------------------------------------------------------
// cheb2: [T3 | T4] = 2 T2 @ [T1 | T2] - [T1 | I].  grid (8, 8), 256 thr.
// ---------------------------------------------------------------------------
__global__ void __launch_bounds__(256) cheb2_kernel(const float* __restrict__ L)
{
    __shared__ alignas(16) char buf[49152];
    int ct = blockIdx.x, nt = blockIdx.y;
    int half = ct >> 2;
    cheb_tile(L, buf, /*aSlot=*/1, /*bSlot=*/half ? 1 : 0,
              /*outSlot=*/half ? 3 : 2, /*dIsL=*/half == 0,
              (ct & 3) * 128, nt);
}

// ---------------------------------------------------------------------------
// Main HMMA GEMM: C[n=512][c=8192] over K'=2048 (single fp16 pass).
// CTA 128x128, 8 warps (4x2), warp 32x64. Grid (64,4), occ 2.
// ---------------------------------------------------------------------------
__global__ void __launch_bounds__(256, 2) hmma_gemm_kernel(float* __restrict__ out)
{
    extern __shared__ char smem[];
    uint32_t sb = smem_u32(smem);
    int tid = threadIdx.x;
    int lane = tid & 31, w = tid >> 5;
    int bx = blockIdx.x;    // c-tile (128 wide)
    int by = blockIdx.y;    // n-tile (128 wide)

    auto load_stage = [&](int s, int i) {
        int kk = i * 64;
        uint32_t sA = sb + s * STAGE_BYTES;
        uint32_t sB = sA + ACHUNK_BYTES;
        #pragma unroll
        for (int q = 0; q < 4; q++) {
            int idx = q * 256 + tid;
            int row = idx >> 3, seg = idx & 7;
            const void* g = g_Ahi + (size_t)(by * 128 + row) * K2 + kk + seg * 8;
            cp_async16(sA + swz(row * 128 + seg * 16), g);
        }
        #pragma unroll
        for (int q = 0; q < 4; q++) {
            int idx = q * 256 + tid;
            int row = idx >> 3, seg = idx & 7;
            const void* g = g_Bhi + (size_t)(bx * 128 + row) * K2 + kk + seg * 8;
            cp_async16(sB + swz(row * 128 + seg * 16), g);
        }
        cp_commit();
    };

    load_stage(0, 0);
    load_stage(1, 1);

    int warp_n0 = (w >> 1) * 32;
    int warp_c0 = (w & 1) * 64;
    int rowA  = warp_n0 + (lane & 15);
    int halfA = lane >> 4;
    int rowB  = warp_c0 + ((lane >> 4) & 1) * 8 + (lane & 7);
    int kselB = (lane >> 3) & 1;

    float acc[2][8][4] = {};

    for (int i = 0; i < NCHUNK; i++) {
        int s = i % STAGES;
        if (i < NCHUNK - 1) cp_wait<1>();
        else                cp_wait<0>();
        __syncthreads();
        if (i + 2 < NCHUNK) load_stage((i + 2) % STAGES, i + 2);

        uint32_t sA = sb + s * STAGE_BYTES;
        uint32_t sB = sA + ACHUNK_BYTES;

        #pragma unroll
        for (int kk = 0; kk < 4; kk++) {
            uint32_t a[2][4];
            #pragma unroll
            for (int m2 = 0; m2 < 2; m2++) {
                uint32_t addr = sA + swz((rowA + m2 * 16) * 128 + (kk * 2 + halfA) * 16);
                ldm_x4(a[m2][0], a[m2][1], a[m2][2], a[m2][3], addr);
            }
            #pragma unroll
            for (int cg = 0; cg < 4; cg++) {
                uint32_t b[4];
                uint32_t addr = sB + swz((rowB + cg * 16) * 128 + (kk * 2 + kselB) * 16);
                ldm_x4(b[0], b[1], b[2], b[3], addr);
                #pragma unroll
                for (int m2 = 0; m2 < 2; m2++) {
                    mma_fp16(acc[m2][2 * cg + 0], a[m2], b + 0);
                    mma_fp16(acc[m2][2 * cg + 1], a[m2], b + 2);
                }
            }
        }
    }

    // Epilogue: + (U0 + bias), write out[b][n][fo]
    int tr = lane >> 2, tc2 = (lane & 3) * 2;
    #pragma unroll
    for (int m2 = 0; m2 < 2; m2++) {
        #pragma unroll
        for (int ct = 0; ct < 8; ct++) {
            int c = bx * 128 + warp_c0 + ct * 8 + tc2;
            int b = c >> 3;
            int n0 = by * 128 + warp_n0 + m2 * 16 + tr;
            size_t o0 = ((size_t)b * NN + n0) * FOUT + tc2;
            size_t o1 = o0 + 8 * FOUT;
            float2 u0 = *reinterpret_cast<const float2*>(&g_U0b[o0]);
            float2 u1 = *reinterpret_cast<const float2*>(&g_U0b[o1]);
            float2 r0 = {acc[m2][ct][0] + u0.x, acc[m2][ct][1] + u0.y};
            float2 r1 = {acc[m2][ct][2] + u1.x, acc[m2][ct][3] + u1.y};
            *reinterpret_cast<float2*>(&out[o0]) = r0;
            *reinterpret_cast<float2*>(&out[o1]) = r1;
        }
    }
}

// ---------------------------------------------------------------------------
extern "C" void kernel_launch(void* const* d_in, const int* in_sizes, int n_in,
                              void* d_out, int out_size)
{
    const float* x = (const float*)d_in[0];  // [1024, 512, 16]
    const float* L = (const float*)d_in[1];  // [512, 512]
    const float* W = (const float*)d_in[2];  // [5, 16, 8]
    const float* b = (const float*)d_in[3];  // [8]
    float* out = (float*)d_out;              // [1024, 512, 8]

    cudaFuncSetAttribute(hmma_gemm_kernel,
                         cudaFuncAttributeMaxDynamicSharedMemorySize, SMEM_TOTAL);

    copy_L_kernel<<<256, 256>>>(L);                    // T1 hi/lo
    prep_kernel<<<dim3(256, 9), 256>>>(x, W, b, L);    // build_u(HMMA) + cheb1
    cheb2_kernel<<<dim3(8, 8), 256>>>(L);              // T3, T4
    hmma_gemm_kernel<<<dim3(64, 4), 256, SMEM_TOTAL>>>(out);
}